// round 6
// baseline (speedup 1.0000x reference)
#include <cuda_runtime.h>
#include <cstdint>

// H2GCNConv: out[:, 0:128]   = segment_sum(w1[e] * x[col1[e]]) over row1
//            out[:, 128:256] = segment_sum(w2[e] * x[col2[e]]) over row2
// N = 50000, d = 128, out is [N, 256] float32.
// edge_index is int32 ([2, E]) — JAX default x64-disabled downcasts the
// "int64" randint to int32.
//
// Strategy: warp-per-edge scatter. Each lane handles one float4 (16B) of the
// 512B feature row: coalesced float4 gather of x[col], scale by w, then one
// red.global.add.v4.f32 per lane into out[row]. 2.4M edges -> 76.8M vector
// REDs. x (25.6MB) + out (51.2MB) fit in L2 (126MB), so this is L2-bound.

#define D 128
#define OUTW 256

__global__ __launch_bounds__(256, 8)
void spmm_scatter_kernel(const float* __restrict__ x,
                         const int* __restrict__ edge_index,  // [2, E] int32
                         const float* __restrict__ edge_w,    // [E]
                         float* __restrict__ out,             // [N, 256]
                         int E, int col_off)
{
    const long long gwarp = ((long long)blockIdx.x * blockDim.x + threadIdx.x) >> 5;
    const int lane = threadIdx.x & 31;
    if (gwarp >= E) return;

    // Broadcast loads: all 32 lanes hit the same address (1 sector each).
    const int   r = __ldg(&edge_index[gwarp]);       // row (dst)
    const int   c = __ldg(&edge_index[E + gwarp]);   // col (src)
    const float w = __ldg(&edge_w[gwarp]);

    // Coalesced 512B gather of x[c]: lane i takes floats [4i, 4i+4).
    const float4* xrow = reinterpret_cast<const float4*>(x + (long long)c * D);
    float4 v = __ldg(&xrow[lane]);
    v.x *= w; v.y *= w; v.z *= w; v.w *= w;

    // One vector reduction per lane (16B, naturally 16B-aligned).
    float* dst = out + (long long)r * OUTW + col_off + lane * 4;
    asm volatile("red.global.add.v4.f32 [%0], {%1, %2, %3, %4};"
                 :: "l"(dst), "f"(v.x), "f"(v.y), "f"(v.z), "f"(v.w)
                 : "memory");
}

extern "C" void kernel_launch(void* const* d_in, const int* in_sizes, int n_in,
                              void* d_out, int out_size)
{
    const float* x   = (const float*)d_in[0];
    const int*   ei1 = (const int*)d_in[1];
    const float* w1  = (const float*)d_in[2];
    const int*   ei2 = (const int*)d_in[3];
    const float* w2  = (const float*)d_in[4];
    float* out = (float*)d_out;

    const int E1 = in_sizes[2];   // edge_w1 element count
    const int E2 = in_sizes[4];   // edge_w2 element count

    // Output is poisoned to 0xAA each run; zero it before accumulation.
    cudaMemsetAsync(d_out, 0, (size_t)out_size * sizeof(float), 0);

    const int threads = 256;                    // 8 warps = 8 edges / block
    {
        long long total = (long long)E1 * 32;
        int blocks = (int)((total + threads - 1) / threads);
        spmm_scatter_kernel<<<blocks, threads>>>(x, ei1, w1, out, E1, 0);
    }
    {
        long long total = (long long)E2 * 32;
        int blocks = (int)((total + threads - 1) / threads);
        spmm_scatter_kernel<<<blocks, threads>>>(x, ei2, w2, out, E2, D);
    }
}

// round 8
// speedup vs baseline: 1.1303x; 1.1303x over previous
#include <cuda_runtime.h>
#include <cstdint>

// H2GCNConv: out[:, 0:128]   = segment_sum(w1[e] * x[col1[e]]) over row1
//            out[:, 128:256] = segment_sum(w2[e] * x[col2[e]]) over row2
// N = 50000, d = 128, out [N,256] f32, edge_index int32 [2,E].
//
// R6 strategy: the scatter version was capped by L2 atomic-ALU throughput
// (~0.74 RED/LTS-slice/cyc). Replace with on-device CSR build + gather:
//   1. zero counts            4. scatter packed (col,w) records by row
//   2. histogram rows         5. warp-per-row gather-reduce, one 512B store
//   3. single-block scan
// No output atomics at all; x-row gathers stay L2-resident.

#define D4 32                 // 128 floats = 32 float4 per row
#define OUTW 256
#define MAXSEG 262144         // >= 2*N cursor/offset slots
#define MAXE   4194304        // >= E1+E2 packed edge records

__device__ int g_cnt[MAXSEG];                  // counts -> scatter cursors
__device__ int g_off[MAXSEG];                  // exclusive row offsets
__device__ unsigned long long g_cw[MAXE];      // packed (col | w<<32), row-sorted

// ---- 1. zero counters ----
__global__ void zero_kernel(int n) {
    int i = blockIdx.x * blockDim.x + threadIdx.x;
    if (i < n) g_cnt[i] = 0;
}

// ---- 2. histogram of destination rows ----
__global__ void hist_kernel(const int* __restrict__ ei, int E, int base) {
    int e = blockIdx.x * blockDim.x + threadIdx.x;
    if (e < E) atomicAdd(&g_cnt[base + __ldg(&ei[e])], 1);
}

// ---- 3. exclusive scan over 2N counts (single block) ----
__global__ void scan_kernel(int n) {
    __shared__ int sh[1024];
    const int tid = threadIdx.x;
    const int per = (n + 1023) >> 10;
    const int lo = tid * per;
    const int hi = min(lo + per, n);
    int s = 0;
    for (int i = lo; i < hi; i++) s += g_cnt[i];
    sh[tid] = s;
    __syncthreads();
    for (int d = 1; d < 1024; d <<= 1) {
        int t = (tid >= d) ? sh[tid - d] : 0;
        __syncthreads();
        sh[tid] += t;
        __syncthreads();
    }
    int run = sh[tid] - s;   // exclusive prefix of this thread's chunk
    for (int i = lo; i < hi; i++) {
        int c = g_cnt[i];
        g_off[i] = run;      // row start
        g_cnt[i] = run;      // scatter cursor
        run += c;
    }
}

// ---- 4. scatter packed (col, w) records into row-sorted order ----
__global__ void scatter_kernel(const int* __restrict__ ei,
                               const float* __restrict__ w,
                               int E, int base) {
    int e = blockIdx.x * blockDim.x + threadIdx.x;
    if (e >= E) return;
    int r = __ldg(&ei[e]);
    int c = __ldg(&ei[E + e]);
    float wv = __ldg(&w[e]);
    int pos = atomicAdd(&g_cnt[base + r], 1);   // cursor ends at row end
    g_cw[pos] = (unsigned long long)(unsigned)c |
                ((unsigned long long)__float_as_uint(wv) << 32);
}

// ---- 5. gather-reduce: one warp per (graph, row), register accumulator ----
__global__ __launch_bounds__(256, 8)
void gather_kernel(const float* __restrict__ x,
                   float* __restrict__ out, int N) {
    const int seg  = (blockIdx.x * blockDim.x + threadIdx.x) >> 5;
    const int lane = threadIdx.x & 31;
    if (seg >= 2 * N) return;
    const int g   = (seg >= N);
    const int row = seg - (g ? N : 0);

    const int start = __ldg(&g_off[seg]);
    const int end   = g_cnt[seg];          // cursor == row end after scatter

    const float4* __restrict__ x4 = reinterpret_cast<const float4*>(x);
    float4 a0 = make_float4(0.f, 0.f, 0.f, 0.f);
    float4 a1 = make_float4(0.f, 0.f, 0.f, 0.f);

    int j = start;
    // 2-way unrolled: two independent x-row gathers in flight per warp.
    for (; j + 1 < end; j += 2) {
        unsigned long long cw0 = __ldg(&g_cw[j]);
        unsigned long long cw1 = __ldg(&g_cw[j + 1]);
        int   c0 = (int)(unsigned)cw0;
        int   c1 = (int)(unsigned)cw1;
        float w0 = __uint_as_float((unsigned)(cw0 >> 32));
        float w1 = __uint_as_float((unsigned)(cw1 >> 32));
        float4 v0 = __ldg(&x4[(long long)c0 * D4 + lane]);
        float4 v1 = __ldg(&x4[(long long)c1 * D4 + lane]);
        a0.x += w0 * v0.x; a0.y += w0 * v0.y; a0.z += w0 * v0.z; a0.w += w0 * v0.w;
        a1.x += w1 * v1.x; a1.y += w1 * v1.y; a1.z += w1 * v1.z; a1.w += w1 * v1.w;
    }
    if (j < end) {
        unsigned long long cw = __ldg(&g_cw[j]);
        int   c = (int)(unsigned)cw;
        float w = __uint_as_float((unsigned)(cw >> 32));
        float4 v = __ldg(&x4[(long long)c * D4 + lane]);
        a0.x += w * v.x; a0.y += w * v.y; a0.z += w * v.z; a0.w += w * v.w;
    }
    a0.x += a1.x; a0.y += a1.y; a0.z += a1.z; a0.w += a1.w;

    // Single coalesced 512B store per row half; also un-poisons the output.
    float4* o4 = reinterpret_cast<float4*>(out + (long long)row * OUTW + g * 128);
    o4[lane] = a0;
}

extern "C" void kernel_launch(void* const* d_in, const int* in_sizes, int n_in,
                              void* d_out, int out_size)
{
    const float* x   = (const float*)d_in[0];
    const int*   ei1 = (const int*)d_in[1];
    const float* w1  = (const float*)d_in[2];
    const int*   ei2 = (const int*)d_in[3];
    const float* w2  = (const float*)d_in[4];
    float* out = (float*)d_out;

    const int E1 = in_sizes[2];
    const int E2 = in_sizes[4];
    const int N  = out_size / OUTW;     // 50000
    const int S  = 2 * N;               // segments: graph1 rows then graph2 rows

    const int T = 256;

    zero_kernel<<<(S + T - 1) / T, T>>>(S);
    hist_kernel<<<(E1 + T - 1) / T, T>>>(ei1, E1, 0);
    hist_kernel<<<(E2 + T - 1) / T, T>>>(ei2, E2, N);
    scan_kernel<<<1, 1024>>>(S);
    scatter_kernel<<<(E1 + T - 1) / T, T>>>(ei1, w1, E1, 0);
    scatter_kernel<<<(E2 + T - 1) / T, T>>>(ei2, w2, E2, N);

    long long gthreads = (long long)S * 32;
    gather_kernel<<<(int)((gthreads + T - 1) / T), T>>>(x, out, N);
}

// round 9
// speedup vs baseline: 2.1361x; 1.8898x over previous
#include <cuda_runtime.h>
#include <cstdint>

// H2GCNConv: out[:, 0:128]   = segment_sum(w1[e] * x[col1[e]]) over row1
//            out[:, 128:256] = segment_sum(w2[e] * x[col2[e]]) over row2
// N = 50000, d = 128, out [N,256] f32, edge_index int32 [2,E].
//
// Pipeline (all graph-capturable, no output atomics):
//   1. zero counts               5. scatter packed (col,w) records by row
//   2. histogram rows            6. warp-per-row gather-reduce,
//   3-4b. two-level parallel        one 512B store per row half
//        exclusive scan (R8: replaces the 143us single-block scan)

#define D4 32                 // 128 floats = 32 float4 per row
#define OUTW 256
#define SCAN_B 1024           // elements per scan block
#define MAXSEG 262144         // >= 2*N cursor/offset slots
#define MAXBLK 1024           // >= ceil(2N / SCAN_B)
#define MAXE   4194304        // >= E1+E2 packed edge records

__device__ int g_cnt[MAXSEG];                  // counts -> scatter cursors
__device__ int g_off[MAXSEG];                  // exclusive row offsets
__device__ int g_blk[MAXBLK];                  // per-block scan totals
__device__ unsigned long long g_cw[MAXE];      // packed (col | w<<32), row-sorted

// ---- 1. zero counters ----
__global__ void zero_kernel(int n) {
    int i = blockIdx.x * blockDim.x + threadIdx.x;
    if (i < n) g_cnt[i] = 0;
}

// ---- 2. histogram of destination rows ----
__global__ void hist_kernel(const int* __restrict__ ei, int E, int base) {
    int e = blockIdx.x * blockDim.x + threadIdx.x;
    if (e < E) atomicAdd(&g_cnt[base + __ldg(&ei[e])], 1);
}

// ---- 3. two-level scan, level A: per-block scan + block totals ----
__global__ void scanA_kernel(int n) {
    __shared__ int sh[SCAN_B];
    const int tid = threadIdx.x;
    const int i = blockIdx.x * SCAN_B + tid;
    int v = (i < n) ? g_cnt[i] : 0;
    sh[tid] = v;
    __syncthreads();
    #pragma unroll
    for (int d = 1; d < SCAN_B; d <<= 1) {
        int t = (tid >= d) ? sh[tid - d] : 0;
        __syncthreads();
        sh[tid] += t;
        __syncthreads();
    }
    if (i < n) g_off[i] = sh[tid] - v;              // local exclusive
    if (tid == SCAN_B - 1) g_blk[blockIdx.x] = sh[tid];  // block total
}

// ---- 4a. level B: exclusive scan of block totals (single small block) ----
__global__ void scanB_kernel(int nblk) {
    __shared__ int sh[MAXBLK];
    const int tid = threadIdx.x;
    int v = (tid < nblk) ? g_blk[tid] : 0;
    sh[tid] = v;
    __syncthreads();
    #pragma unroll
    for (int d = 1; d < MAXBLK; d <<= 1) {
        int t = (tid >= d) ? sh[tid - d] : 0;
        __syncthreads();
        sh[tid] += t;
        __syncthreads();
    }
    if (tid < nblk) g_blk[tid] = sh[tid] - v;       // exclusive
}

// ---- 4b. level C: add block offsets, mirror into cursors ----
__global__ void scanC_kernel(int n) {
    const int i = blockIdx.x * SCAN_B + threadIdx.x;
    if (i < n) {
        int o = g_off[i] + g_blk[blockIdx.x];
        g_off[i] = o;
        g_cnt[i] = o;                                // scatter cursor
    }
}

// ---- 5. scatter packed (col, w) records into row-sorted order ----
__global__ void scatter_kernel(const int* __restrict__ ei,
                               const float* __restrict__ w,
                               int E, int base) {
    int e = blockIdx.x * blockDim.x + threadIdx.x;
    if (e >= E) return;
    int r = __ldg(&ei[e]);
    int c = __ldg(&ei[E + e]);
    float wv = __ldg(&w[e]);
    int pos = atomicAdd(&g_cnt[base + r], 1);        // cursor ends at row end
    g_cw[pos] = (unsigned long long)(unsigned)c |
                ((unsigned long long)__float_as_uint(wv) << 32);
}

// ---- 6. gather-reduce: one warp per (graph, row), register accumulator ----
__global__ __launch_bounds__(256, 8)
void gather_kernel(const float* __restrict__ x,
                   float* __restrict__ out, int N) {
    const int seg  = (blockIdx.x * blockDim.x + threadIdx.x) >> 5;
    const int lane = threadIdx.x & 31;
    if (seg >= 2 * N) return;
    const int g   = (seg >= N);
    const int row = seg - (g ? N : 0);

    const int start = __ldg(&g_off[seg]);
    const int end   = g_cnt[seg];          // cursor == row end after scatter

    const float4* __restrict__ x4 = reinterpret_cast<const float4*>(x);
    float4 a0 = make_float4(0.f, 0.f, 0.f, 0.f);
    float4 a1 = make_float4(0.f, 0.f, 0.f, 0.f);

    int j = start;
    for (; j + 1 < end; j += 2) {
        unsigned long long cw0 = __ldg(&g_cw[j]);
        unsigned long long cw1 = __ldg(&g_cw[j + 1]);
        int   c0 = (int)(unsigned)cw0;
        int   c1 = (int)(unsigned)cw1;
        float w0 = __uint_as_float((unsigned)(cw0 >> 32));
        float w1 = __uint_as_float((unsigned)(cw1 >> 32));
        float4 v0 = __ldg(&x4[(long long)c0 * D4 + lane]);
        float4 v1 = __ldg(&x4[(long long)c1 * D4 + lane]);
        a0.x += w0 * v0.x; a0.y += w0 * v0.y; a0.z += w0 * v0.z; a0.w += w0 * v0.w;
        a1.x += w1 * v1.x; a1.y += w1 * v1.y; a1.z += w1 * v1.z; a1.w += w1 * v1.w;
    }
    if (j < end) {
        unsigned long long cw = __ldg(&g_cw[j]);
        int   c = (int)(unsigned)cw;
        float w = __uint_as_float((unsigned)(cw >> 32));
        float4 v = __ldg(&x4[(long long)c * D4 + lane]);
        a0.x += w * v.x; a0.y += w * v.y; a0.z += w * v.z; a0.w += w * v.w;
    }
    a0.x += a1.x; a0.y += a1.y; a0.z += a1.z; a0.w += a1.w;

    // Single coalesced 512B store per row half; also un-poisons the output.
    float4* o4 = reinterpret_cast<float4*>(out + (long long)row * OUTW + g * 128);
    o4[lane] = a0;
}

extern "C" void kernel_launch(void* const* d_in, const int* in_sizes, int n_in,
                              void* d_out, int out_size)
{
    const float* x   = (const float*)d_in[0];
    const int*   ei1 = (const int*)d_in[1];
    const float* w1  = (const float*)d_in[2];
    const int*   ei2 = (const int*)d_in[3];
    const float* w2  = (const float*)d_in[4];
    float* out = (float*)d_out;

    const int E1 = in_sizes[2];
    const int E2 = in_sizes[4];
    const int N  = out_size / OUTW;     // 50000
    const int S  = 2 * N;               // segments: graph1 rows then graph2 rows
    const int nblk = (S + SCAN_B - 1) / SCAN_B;

    const int T = 256;

    zero_kernel<<<(S + T - 1) / T, T>>>(S);
    hist_kernel<<<(E1 + T - 1) / T, T>>>(ei1, E1, 0);
    hist_kernel<<<(E2 + T - 1) / T, T>>>(ei2, E2, N);
    scanA_kernel<<<nblk, SCAN_B>>>(S);
    scanB_kernel<<<1, MAXBLK>>>(nblk);
    scanC_kernel<<<nblk, SCAN_B>>>(S);
    scatter_kernel<<<(E1 + T - 1) / T, T>>>(ei1, w1, E1, 0);
    scatter_kernel<<<(E2 + T - 1) / T, T>>>(ei2, w2, E2, N);

    long long gthreads = (long long)S * 32;
    gather_kernel<<<(int)((gthreads + T - 1) / T), T>>>(x, out, N);
}